// round 16
// baseline (speedup 1.0000x reference)
#include <cuda_runtime.h>
#include <cuda_fp16.h>
#include <cstdint>

// ---------------------------------------------------------------------------
// complexGRUCell: B=16384, I=256, H=256, fp32 in/out.
// fp16 tensor-core GEMMs (mma.m16n8k16) with ldmatrix + 4-stage cp.async.
// CTA 128x128, 4 warps (2m x 2n), warp tile 64x64, 2 CTA/SM, BK=32,
// fragment software pipeline. convA/e1/e2/preps vectorized.
// __device__ globals resolved INSIDE device code (GB300/ATS host-shadow trap).
// ---------------------------------------------------------------------------

#define B_ROWS 16384
#define HDIM   256
#define G1_N   1536
#define G1_K   1024
#define G2_N   512
#define G2_K   512

__device__ __half g_G1h[G1_N * G1_K];
__device__ __half g_G2h[G2_N * G2_K];
__device__ __half g_Ah[(size_t)B_ROWS * G1_K];
__device__ __half g_RHh[(size_t)B_ROWS * 512];
__device__ float  g_bias[G1_N];
__device__ __half g_C1h[(size_t)B_ROWS * G1_N];
__device__ __half g_C2h[(size_t)B_ROWS * 512];

// ---- PTX helpers ------------------------------------------------------------
__device__ __forceinline__ uint32_t smem_u32(const void* p) {
    uint32_t a;
    asm("{ .reg .u64 t; cvta.to.shared.u64 t, %1; cvt.u32.u64 %0, t; }"
        : "=r"(a) : "l"(p));
    return a;
}
__device__ __forceinline__ void cp16(uint32_t s, const void* g) {
    asm volatile("cp.async.cg.shared.global [%0], [%1], 16;" :: "r"(s), "l"(g));
}
__device__ __forceinline__ void cp_commit() {
    asm volatile("cp.async.commit_group;" ::: "memory");
}
__device__ __forceinline__ void cp_wait2() {
    asm volatile("cp.async.wait_group 2;" ::: "memory");
}
__device__ __forceinline__ void cp_wait1() {
    asm volatile("cp.async.wait_group 1;" ::: "memory");
}
__device__ __forceinline__ void cp_wait0() {
    asm volatile("cp.async.wait_group 0;" ::: "memory");
}
__device__ __forceinline__ void ldsm4(uint32_t* r, uint32_t addr) {
    asm volatile("ldmatrix.sync.aligned.m8n8.x4.shared.b16 {%0,%1,%2,%3}, [%4];"
                 : "=r"(r[0]), "=r"(r[1]), "=r"(r[2]), "=r"(r[3]) : "r"(addr));
}
__device__ __forceinline__ void mma_f16(float* c, const uint32_t* a,
                                        const uint32_t* b) {
    asm volatile(
        "mma.sync.aligned.m16n8k16.row.col.f32.f16.f16.f32 "
        "{%0,%1,%2,%3}, {%4,%5,%6,%7}, {%8,%9}, {%0,%1,%2,%3};"
        : "+f"(c[0]), "+f"(c[1]), "+f"(c[2]), "+f"(c[3])
        : "r"(a[0]), "r"(a[1]), "r"(a[2]), "r"(a[3]), "r"(b[0]), "r"(b[1]));
}
__device__ __forceinline__ float sigmoidf_(float x) {
    return 1.0f / (1.0f + __expf(-x));
}

// ---- weight preparation (4 k per thread) --------------------------------------
__global__ void prep_g1(const float* __restrict__ wr_re, const float* __restrict__ wr_im,
                        const float* __restrict__ wz_re, const float* __restrict__ wz_im,
                        const float* __restrict__ wh_re, const float* __restrict__ wh_im,
                        const float* __restrict__ ur_re, const float* __restrict__ ur_im,
                        const float* __restrict__ uz_re, const float* __restrict__ uz_im,
                        const float* __restrict__ uh_re, const float* __restrict__ uh_im)
{
    int idx = blockIdx.x * blockDim.x + threadIdx.x;   // < G1_N * 256
    int n  = idx >> 8;
    int kq = (idx & 255) << 2;          // 4-aligned, same kg for all 4
    int g = n >> 8,  j = n & 255;
    int kg = kq >> 8, kc = kq & 255;

    const float *Wre, *Wim, *Ure, *Uim;
    if (g < 2)      { Wre = wr_re; Wim = wr_im; Ure = ur_re; Uim = ur_im; }
    else if (g < 4) { Wre = wz_re; Wim = wz_im; Ure = uz_re; Uim = uz_im; }
    else            { Wre = wh_re; Wim = wh_im; Ure = uh_re; Uim = uh_im; }
    bool isIm = (g & 1) != 0;
    bool isH  = (g >= 4);

    int wj = j * 512;
    int uj = j * 256;
    float v[4];
    if (kg == 0) {
        float4 w = *(const float4*)((isIm ? Wim : Wre) + wj + kc);
        v[0] = w.x; v[1] = w.y; v[2] = w.z; v[3] = w.w;
    } else if (kg == 1) {
        float4 w = *(const float4*)((isIm ? Wre : Wim) + wj + kc);
        float s = isIm ? 1.f : -1.f;
        v[0] = s * w.x; v[1] = s * w.y; v[2] = s * w.z; v[3] = s * w.w;
    } else if (kg == 2) {
        float4 u = *(const float4*)((isIm ? Uim : Ure) + uj + kc);
        float4 w = make_float4(0.f, 0.f, 0.f, 0.f);
        if (!isH) w = *(const float4*)((isIm ? Wim : Wre) + wj + 256 + kc);
        v[0] = w.x + u.x; v[1] = w.y + u.y; v[2] = w.z + u.z; v[3] = w.w + u.w;
    } else {
        float4 u = *(const float4*)((isIm ? Ure : Uim) + uj + kc);
        float4 w = make_float4(0.f, 0.f, 0.f, 0.f);
        if (!isH) w = *(const float4*)((isIm ? Wre : Wim) + wj + 256 + kc);
        float s = isIm ? 1.f : -1.f;
        v[0] = s * (w.x + u.x); v[1] = s * (w.y + u.y);
        v[2] = s * (w.z + u.z); v[3] = s * (w.w + u.w);
    }
    __half2 h0 = __floats2half2_rn(v[0], v[1]);
    __half2 h1 = __floats2half2_rn(v[2], v[3]);
    uint2 o;
    o.x = *(uint32_t*)&h0; o.y = *(uint32_t*)&h1;
    *(uint2*)(g_G1h + (size_t)n * G1_K + kq) = o;
}

__global__ void prep_g2(const float* __restrict__ wh_re,
                        const float* __restrict__ wh_im)
{
    int idx = blockIdx.x * blockDim.x + threadIdx.x;   // < G2_N * 128
    int n  = idx >> 7;
    int kq = (idx & 127) << 2;
    int g = n >> 8,  j = n & 255;
    int kg = kq >> 8, kc = kq & 255;

    float4 w = *(const float4*)(((g == 0) == (kg == 0) ? wh_re : wh_im)
                                + j * 512 + 256 + kc);
    float s = (g == 0 && kg == 1) ? -1.f : 1.f;
    __half2 h0 = __floats2half2_rn(s * w.x, s * w.y);
    __half2 h1 = __floats2half2_rn(s * w.z, s * w.w);
    uint2 o;
    o.x = *(uint32_t*)&h0; o.y = *(uint32_t*)&h1;
    *(uint2*)(g_G2h + (size_t)n * G2_K + kq) = o;
}

__global__ void prep_bias(const float* __restrict__ wr_b_re, const float* __restrict__ wr_b_im,
                          const float* __restrict__ wz_b_re, const float* __restrict__ wz_b_im,
                          const float* __restrict__ wh_b_re, const float* __restrict__ wh_b_im)
{
    int idx = blockIdx.x * blockDim.x + threadIdx.x;
    int g = idx >> 8, j = idx & 255;
    const float *br, *bi;
    if (g < 2)      { br = wr_b_re; bi = wr_b_im; }
    else if (g < 4) { br = wz_b_re; bi = wz_b_im; }
    else            { br = wh_b_re; bi = wh_b_im; }
    g_bias[idx] = (g & 1) ? (br[j] + bi[j]) : (br[j] - bi[j]);
}

// ---- convA: 8 halves per thread ------------------------------------------------
__global__ void convA(const float* __restrict__ x_re, const float* __restrict__ x_im,
                      const float* __restrict__ h_re, const float* __restrict__ h_im)
{
    int idx = blockIdx.x * blockDim.x + threadIdx.x;   // < B*128
    int b = idx >> 7;
    int k = (idx & 127) << 3;
    int plane = k >> 8, kc = k & 255;
    const float* src = (plane == 0) ? x_re : (plane == 1) ? x_im
                     : (plane == 2) ? h_re : h_im;
    const float* p = src + (size_t)b * 256 + kc;
    float4 v0 = *(const float4*)p;
    float4 v1 = *(const float4*)(p + 4);
    __half2 h0 = __floats2half2_rn(v0.x, v0.y);
    __half2 h1 = __floats2half2_rn(v0.z, v0.w);
    __half2 h2 = __floats2half2_rn(v1.x, v1.y);
    __half2 h3 = __floats2half2_rn(v1.z, v1.w);
    uint4 o;
    o.x = *(uint32_t*)&h0; o.y = *(uint32_t*)&h1;
    o.z = *(uint32_t*)&h2; o.w = *(uint32_t*)&h3;
    *(uint4*)(g_Ah + (size_t)b * 1024 + k) = o;
}

// ---- fp16 tensor-core GEMM: C[M,N] = A[M,K] @ W[N,K]^T, C in fp16 ----------
#define BM 128
#define BN 128
#define BKH 32
#define ROWB 80                        // bytes per smem row (64 + 16 pad)
#define A_ST (BM * ROWB)               // 10240
#define STAGE_B (2 * A_ST)             // 20480
#define STAGES 4
#define HG_SMEM (STAGES * STAGE_B)     // 81920

__global__ void __launch_bounds__(128, 2)
hgemm(int mode)
{
    extern __shared__ char smem[];
    const uint32_t sb = smem_u32(smem);

    const __half* A;
    const __half* W;
    __half* C;
    int lda, N, K;
    if (mode == 0) {
        A = g_Ah;  W = g_G1h; C = g_C1h; lda = G1_K; N = G1_N; K = G1_K;
    } else {
        A = g_RHh; W = g_G2h; C = g_C2h; lda = G2_K; N = G2_N; K = G2_K;
    }

    const int tid  = threadIdx.x;
    const int lane = tid & 31;
    const int wid  = tid >> 5;
    const int wm   = wid & 1;
    const int wn   = wid >> 1;
    const int mBlk = blockIdx.y * BM;
    const int nBlk = blockIdx.x * BN;
    const int NK   = K / BKH;

    // loader: 128 threads; 4 A-rows + 4 B-rows of 16B per stage
    const int lrow = tid >> 2;
    const int seg  = tid & 3;
    const __half* gA[4];
    const __half* gB[4];
    uint32_t sA[4], sB[4];
#pragma unroll
    for (int i = 0; i < 4; ++i) {
        gA[i] = A + (size_t)(mBlk + lrow + 32 * i) * lda + seg * 8;
        gB[i] = W + (size_t)(nBlk + lrow + 32 * i) * K   + seg * 8;
        sA[i] = sb + (lrow + 32 * i) * ROWB + seg * 16;
        sB[i] = sA[i] + A_ST;
    }

    // ldmatrix lane offsets (verified fragment layout)
    const int aRow = lane & 15;
    const int aK   = (lane >> 4) << 3;
    uint32_t aOff[4];
#pragma unroll
    for (int mt = 0; mt < 4; ++mt)
        aOff[mt] = (uint32_t)((wm * 64 + mt * 16 + aRow) * ROWB + aK * 2);
    const int bRow = ((lane >> 4) << 3) + (lane & 7);
    const int bK   = lane & 8;
    uint32_t bOff[4];
#pragma unroll
    for (int p = 0; p < 4; ++p)
        bOff[p] = (uint32_t)(A_ST + (wn * 64 + p * 16 + bRow) * ROWB + bK * 2);

    float c[4][8][4];
#pragma unroll
    for (int i = 0; i < 4; ++i)
#pragma unroll
        for (int j = 0; j < 8; ++j)
#pragma unroll
            for (int r = 0; r < 4; ++r) c[i][j][r] = 0.f;

    auto load = [&](int st, int k) {
        uint32_t off = (uint32_t)(st * STAGE_B);
        int kh = k * BKH;
#pragma unroll
        for (int i = 0; i < 4; ++i) {
            cp16(sA[i] + off, gA[i] + kh);
            cp16(sB[i] + off, gB[i] + kh);
        }
    };

    load(0, 0); cp_commit();
    load(1, 1); cp_commit();
    load(2, 2); cp_commit();

    for (int k = 0; k < NK; ++k) {
        if (k + 2 < NK)      cp_wait2();
        else if (k + 1 < NK) cp_wait1();
        else                 cp_wait0();
        __syncthreads();

        const uint32_t base = (uint32_t)((k % STAGES) * STAGE_B);

        uint32_t a[2][4][4], b[2][4][4];
#pragma unroll
        for (int mt = 0; mt < 4; ++mt)
            ldsm4(a[0][mt], sb + base + aOff[mt]);
#pragma unroll
        for (int p = 0; p < 4; ++p)
            ldsm4(b[0][p], sb + base + bOff[p]);
#pragma unroll
        for (int mt = 0; mt < 4; ++mt)
            ldsm4(a[1][mt], sb + base + aOff[mt] + 32);
#pragma unroll
        for (int p = 0; p < 4; ++p)
            ldsm4(b[1][p], sb + base + bOff[p] + 32);

        if (k + 3 < NK) {
            load((k + 3) % STAGES, k + 3);
            cp_commit();
        }

#pragma unroll
        for (int kk = 0; kk < 2; ++kk)
#pragma unroll
            for (int mt = 0; mt < 4; ++mt)
#pragma unroll
                for (int nt = 0; nt < 8; ++nt)
                    mma_f16(c[mt][nt], a[kk][mt], &b[kk][nt >> 1][(nt & 1) * 2]);
    }

    // epilogue: fp32 acc -> fp16 C
    const int grp = lane >> 2;
    const int qid = lane & 3;
#pragma unroll
    for (int mt = 0; mt < 4; ++mt) {
#pragma unroll
        for (int nt = 0; nt < 8; ++nt) {
            int row = mBlk + wm * 64 + mt * 16 + grp;
            int col = nBlk + wn * 64 + nt * 8 + qid * 2;
            *(__half2*)&C[(size_t)row * N + col] =
                __floats2half2_rn(c[mt][nt][0], c[mt][nt][1]);
            *(__half2*)&C[(size_t)(row + 8) * N + col] =
                __floats2half2_rn(c[mt][nt][2], c[mt][nt][3]);
        }
    }
}

// ---- elementwise: 4 j per thread ----------------------------------------------
__global__ void e1_kernel(const float* __restrict__ h_re,
                          const float* __restrict__ h_im)
{
    int idx = blockIdx.x * blockDim.x + threadIdx.x;   // < B*64
    int b = idx >> 6;
    int j = (idx & 63) << 2;
    size_t row = (size_t)b * G1_N;

    uint2 cr_u = *(const uint2*)&g_C1h[row + j];
    uint2 ci_u = *(const uint2*)&g_C1h[row + 256 + j];
    const __half* cr = (const __half*)&cr_u;
    const __half* ci = (const __half*)&ci_u;
    float4 br4 = *(const float4*)&g_bias[j];
    float4 bi4 = *(const float4*)&g_bias[256 + j];
    float4 hr4 = *(const float4*)&h_re[(size_t)b * 256 + j];
    float4 hi4 = *(const float4*)&h_im[(size_t)b * 256 + j];
    const float* brp = &br4.x; const float* bip = &bi4.x;
    const float* hrp = &hr4.x; const float* hip = &hi4.x;

    __half rout[4], iout[4];
#pragma unroll
    for (int q = 0; q < 4; ++q) {
        float rr = sigmoidf_(__half2float(cr[q]) + brp[q]);
        float ri = sigmoidf_(__half2float(ci[q]) + bip[q]);
        rout[q] = __float2half(rr * hrp[q] - ri * hip[q]);
        iout[q] = __float2half(rr * hip[q] + ri * hrp[q]);
    }
    size_t r2 = (size_t)b * 512;
    *(uint2*)&g_RHh[r2 + j]       = *(uint2*)rout;
    *(uint2*)&g_RHh[r2 + 256 + j] = *(uint2*)iout;
}

__global__ void e2_kernel(const float* __restrict__ h_re,
                          const float* __restrict__ h_im,
                          float* __restrict__ out)
{
    int idx = blockIdx.x * blockDim.x + threadIdx.x;   // < B*64
    int b = idx >> 6;
    int j = (idx & 63) << 2;
    size_t r1 = (size_t)b * G1_N;
    size_t r2 = (size_t)b * 512;

    uint2 zr_u = *(const uint2*)&g_C1h[r1 + 512 + j];
    uint2 zi_u = *(const uint2*)&g_C1h[r1 + 768 + j];
    uint2 pr_u = *(const uint2*)&g_C1h[r1 + 1024 + j];
    uint2 pi_u = *(const uint2*)&g_C1h[r1 + 1280 + j];
    uint2 c2r_u = *(const uint2*)&g_C2h[r2 + j];
    uint2 c2i_u = *(const uint2*)&g_C2h[r2 + 256 + j];
    const __half* zrh = (const __half*)&zr_u;
    const __half* zih = (const __half*)&zi_u;
    const __half* prh = (const __half*)&pr_u;
    const __half* pih = (const __half*)&pi_u;
    const __half* c2r = (const __half*)&c2r_u;
    const __half* c2i = (const __half*)&c2i_u;

    float4 bzr4 = *(const float4*)&g_bias[512 + j];
    float4 bzi4 = *(const float4*)&g_bias[768 + j];
    float4 bpr4 = *(const float4*)&g_bias[1024 + j];
    float4 bpi4 = *(const float4*)&g_bias[1280 + j];
    float4 hr4  = *(const float4*)&h_re[(size_t)b * 256 + j];
    float4 hi4  = *(const float4*)&h_im[(size_t)b * 256 + j];
    const float* bzr = &bzr4.x; const float* bzi = &bzi4.x;
    const float* bpr = &bpr4.x; const float* bpi = &bpi4.x;
    const float* hrp = &hr4.x;  const float* hip = &hi4.x;

    float ore[4], oim[4];
#pragma unroll
    for (int q = 0; q < 4; ++q) {
        float zr = sigmoidf_(__half2float(zrh[q]) + bzr[q]);
        float zi = sigmoidf_(__half2float(zih[q]) + bzi[q]);
        float er = __half2float(c2r[q]) + __half2float(prh[q]) + bpr[q];
        float ei = __half2float(c2i[q]) + __half2float(pih[q]) + bpi[q];
        float hhr = tanhf(er);
        float hhi = tanhf(ei);
        float hr = hrp[q], hi = hip[q];
        ore[q] = (1.0f - zr) * hr + zi * hi + zr * hhr - zi * hhi;
        oim[q] = (1.0f - zr) * hi - zi * hr + zr * hhi + zi * hhr;
    }
    *(float4*)&out[(size_t)b * 256 + j] = *(float4*)ore;
    *(float4*)&out[(size_t)B_ROWS * HDIM + (size_t)b * 256 + j] = *(float4*)oim;
}

// ---- launch -------------------------------------------------------------------
extern "C" void kernel_launch(void* const* d_in, const int* in_sizes, int n_in,
                              void* d_out, int out_size)
{
    const float* x_re    = (const float*)d_in[0];
    const float* x_im    = (const float*)d_in[1];
    const float* h_re    = (const float*)d_in[2];
    const float* h_im    = (const float*)d_in[3];
    const float* wr_w_re = (const float*)d_in[4];
    const float* wr_w_im = (const float*)d_in[5];
    const float* wr_b_re = (const float*)d_in[6];
    const float* wr_b_im = (const float*)d_in[7];
    const float* wz_w_re = (const float*)d_in[8];
    const float* wz_w_im = (const float*)d_in[9];
    const float* wz_b_re = (const float*)d_in[10];
    const float* wz_b_im = (const float*)d_in[11];
    const float* wh_w_re = (const float*)d_in[12];
    const float* wh_w_im = (const float*)d_in[13];
    const float* wh_b_re = (const float*)d_in[14];
    const float* wh_b_im = (const float*)d_in[15];
    const float* ur_w_re = (const float*)d_in[16];
    const float* ur_w_im = (const float*)d_in[17];
    const float* uz_w_re = (const float*)d_in[18];
    const float* uz_w_im = (const float*)d_in[19];
    const float* uh_w_re = (const float*)d_in[20];
    const float* uh_w_im = (const float*)d_in[21];

    static int smem_set = 0;
    if (!smem_set) {
        cudaFuncSetAttribute(hgemm, cudaFuncAttributeMaxDynamicSharedMemorySize,
                             HG_SMEM);
        smem_set = 1;
    }

    prep_g1<<<(G1_N * 256) / 256, 256>>>(wr_w_re, wr_w_im, wz_w_re, wz_w_im,
                                         wh_w_re, wh_w_im, ur_w_re, ur_w_im,
                                         uz_w_re, uz_w_im, uh_w_re, uh_w_im);
    prep_g2<<<(G2_N * 128) / 256, 256>>>(wh_w_re, wh_w_im);
    prep_bias<<<G1_N / 256, 256>>>(wr_b_re, wr_b_im, wz_b_re, wz_b_im,
                                   wh_b_re, wh_b_im);
    convA<<<(B_ROWS * 128) / 256, 256>>>(x_re, x_im, h_re, h_im);

    dim3 blk(128);
    dim3 grid1(G1_N / BN, B_ROWS / BM);   // 12 x 128
    hgemm<<<grid1, blk, HG_SMEM>>>(0);

    e1_kernel<<<(B_ROWS * 64) / 256, 256>>>(h_re, h_im);

    dim3 grid2(G2_N / BN, B_ROWS / BM);   // 4 x 128
    hgemm<<<grid2, blk, HG_SMEM>>>(1);

    e2_kernel<<<(B_ROWS * 64) / 256, 256>>>(h_re, h_im, (float*)d_out);
}

// round 17
// speedup vs baseline: 1.0146x; 1.0146x over previous
#include <cuda_runtime.h>
#include <cuda_fp16.h>
#include <cstdint>

// ---------------------------------------------------------------------------
// complexGRUCell: B=16384, I=256, H=256, fp32 in/out.
// fp16 tensor-core GEMMs (mma.m16n8k16) with ldmatrix + 3-stage cp.async.
// CTA 128x128, 4 warps (2m x 2n), warp tile 64x64, 2 CTA/SM, BK=32,
// fragment software pipeline. convA/e1/e2/preps vectorized.
// __device__ globals resolved INSIDE device code (GB300/ATS host-shadow trap).
// ---------------------------------------------------------------------------

#define B_ROWS 16384
#define HDIM   256
#define G1_N   1536
#define G1_K   1024
#define G2_N   512
#define G2_K   512

__device__ __half g_G1h[G1_N * G1_K];
__device__ __half g_G2h[G2_N * G2_K];
__device__ __half g_Ah[(size_t)B_ROWS * G1_K];
__device__ __half g_RHh[(size_t)B_ROWS * 512];
__device__ float  g_bias[G1_N];
__device__ __half g_C1h[(size_t)B_ROWS * G1_N];
__device__ __half g_C2h[(size_t)B_ROWS * 512];

// ---- PTX helpers ------------------------------------------------------------
__device__ __forceinline__ uint32_t smem_u32(const void* p) {
    uint32_t a;
    asm("{ .reg .u64 t; cvta.to.shared.u64 t, %1; cvt.u32.u64 %0, t; }"
        : "=r"(a) : "l"(p));
    return a;
}
__device__ __forceinline__ void cp16(uint32_t s, const void* g) {
    asm volatile("cp.async.cg.shared.global [%0], [%1], 16;" :: "r"(s), "l"(g));
}
__device__ __forceinline__ void cp_commit() {
    asm volatile("cp.async.commit_group;" ::: "memory");
}
__device__ __forceinline__ void cp_wait1() {
    asm volatile("cp.async.wait_group 1;" ::: "memory");
}
__device__ __forceinline__ void cp_wait0() {
    asm volatile("cp.async.wait_group 0;" ::: "memory");
}
__device__ __forceinline__ void ldsm4(uint32_t* r, uint32_t addr) {
    asm volatile("ldmatrix.sync.aligned.m8n8.x4.shared.b16 {%0,%1,%2,%3}, [%4];"
                 : "=r"(r[0]), "=r"(r[1]), "=r"(r[2]), "=r"(r[3]) : "r"(addr));
}
__device__ __forceinline__ void mma_f16(float* c, const uint32_t* a,
                                        const uint32_t* b) {
    asm volatile(
        "mma.sync.aligned.m16n8k16.row.col.f32.f16.f16.f32 "
        "{%0,%1,%2,%3}, {%4,%5,%6,%7}, {%8,%9}, {%0,%1,%2,%3};"
        : "+f"(c[0]), "+f"(c[1]), "+f"(c[2]), "+f"(c[3])
        : "r"(a[0]), "r"(a[1]), "r"(a[2]), "r"(a[3]), "r"(b[0]), "r"(b[1]));
}
__device__ __forceinline__ float sigmoidf_(float x) {
    return 1.0f / (1.0f + __expf(-x));
}

// ---- weight preparation (4 k per thread) --------------------------------------
__global__ void prep_g1(const float* __restrict__ wr_re, const float* __restrict__ wr_im,
                        const float* __restrict__ wz_re, const float* __restrict__ wz_im,
                        const float* __restrict__ wh_re, const float* __restrict__ wh_im,
                        const float* __restrict__ ur_re, const float* __restrict__ ur_im,
                        const float* __restrict__ uz_re, const float* __restrict__ uz_im,
                        const float* __restrict__ uh_re, const float* __restrict__ uh_im)
{
    int idx = blockIdx.x * blockDim.x + threadIdx.x;   // < G1_N * 256
    int n  = idx >> 8;
    int kq = (idx & 255) << 2;          // 4-aligned, same kg for all 4
    int g = n >> 8,  j = n & 255;
    int kg = kq >> 8, kc = kq & 255;

    const float *Wre, *Wim, *Ure, *Uim;
    if (g < 2)      { Wre = wr_re; Wim = wr_im; Ure = ur_re; Uim = ur_im; }
    else if (g < 4) { Wre = wz_re; Wim = wz_im; Ure = uz_re; Uim = uz_im; }
    else            { Wre = wh_re; Wim = wh_im; Ure = uh_re; Uim = uh_im; }
    bool isIm = (g & 1) != 0;
    bool isH  = (g >= 4);

    int wj = j * 512;
    int uj = j * 256;
    float v[4];
    if (kg == 0) {
        float4 w = *(const float4*)((isIm ? Wim : Wre) + wj + kc);
        v[0] = w.x; v[1] = w.y; v[2] = w.z; v[3] = w.w;
    } else if (kg == 1) {
        float4 w = *(const float4*)((isIm ? Wre : Wim) + wj + kc);
        float s = isIm ? 1.f : -1.f;
        v[0] = s * w.x; v[1] = s * w.y; v[2] = s * w.z; v[3] = s * w.w;
    } else if (kg == 2) {
        float4 u = *(const float4*)((isIm ? Uim : Ure) + uj + kc);
        float4 w = make_float4(0.f, 0.f, 0.f, 0.f);
        if (!isH) w = *(const float4*)((isIm ? Wim : Wre) + wj + 256 + kc);
        v[0] = w.x + u.x; v[1] = w.y + u.y; v[2] = w.z + u.z; v[3] = w.w + u.w;
    } else {
        float4 u = *(const float4*)((isIm ? Ure : Uim) + uj + kc);
        float4 w = make_float4(0.f, 0.f, 0.f, 0.f);
        if (!isH) w = *(const float4*)((isIm ? Wre : Wim) + wj + 256 + kc);
        float s = isIm ? 1.f : -1.f;
        v[0] = s * (w.x + u.x); v[1] = s * (w.y + u.y);
        v[2] = s * (w.z + u.z); v[3] = s * (w.w + u.w);
    }
    __half2 h0 = __floats2half2_rn(v[0], v[1]);
    __half2 h1 = __floats2half2_rn(v[2], v[3]);
    uint2 o;
    o.x = *(uint32_t*)&h0; o.y = *(uint32_t*)&h1;
    *(uint2*)(g_G1h + (size_t)n * G1_K + kq) = o;
}

__global__ void prep_g2(const float* __restrict__ wh_re,
                        const float* __restrict__ wh_im)
{
    int idx = blockIdx.x * blockDim.x + threadIdx.x;   // < G2_N * 128
    int n  = idx >> 7;
    int kq = (idx & 127) << 2;
    int g = n >> 8,  j = n & 255;
    int kg = kq >> 8, kc = kq & 255;

    float4 w = *(const float4*)(((g == 0) == (kg == 0) ? wh_re : wh_im)
                                + j * 512 + 256 + kc);
    float s = (g == 0 && kg == 1) ? -1.f : 1.f;
    __half2 h0 = __floats2half2_rn(s * w.x, s * w.y);
    __half2 h1 = __floats2half2_rn(s * w.z, s * w.w);
    uint2 o;
    o.x = *(uint32_t*)&h0; o.y = *(uint32_t*)&h1;
    *(uint2*)(g_G2h + (size_t)n * G2_K + kq) = o;
}

__global__ void prep_bias(const float* __restrict__ wr_b_re, const float* __restrict__ wr_b_im,
                          const float* __restrict__ wz_b_re, const float* __restrict__ wz_b_im,
                          const float* __restrict__ wh_b_re, const float* __restrict__ wh_b_im)
{
    int idx = blockIdx.x * blockDim.x + threadIdx.x;
    int g = idx >> 8, j = idx & 255;
    const float *br, *bi;
    if (g < 2)      { br = wr_b_re; bi = wr_b_im; }
    else if (g < 4) { br = wz_b_re; bi = wz_b_im; }
    else            { br = wh_b_re; bi = wh_b_im; }
    g_bias[idx] = (g & 1) ? (br[j] + bi[j]) : (br[j] - bi[j]);
}

// ---- convA: 8 halves per thread ------------------------------------------------
__global__ void convA(const float* __restrict__ x_re, const float* __restrict__ x_im,
                      const float* __restrict__ h_re, const float* __restrict__ h_im)
{
    int idx = blockIdx.x * blockDim.x + threadIdx.x;   // < B*128
    int b = idx >> 7;
    int k = (idx & 127) << 3;
    int plane = k >> 8, kc = k & 255;
    const float* src = (plane == 0) ? x_re : (plane == 1) ? x_im
                     : (plane == 2) ? h_re : h_im;
    const float* p = src + (size_t)b * 256 + kc;
    float4 v0 = *(const float4*)p;
    float4 v1 = *(const float4*)(p + 4);
    __half2 h0 = __floats2half2_rn(v0.x, v0.y);
    __half2 h1 = __floats2half2_rn(v0.z, v0.w);
    __half2 h2 = __floats2half2_rn(v1.x, v1.y);
    __half2 h3 = __floats2half2_rn(v1.z, v1.w);
    uint4 o;
    o.x = *(uint32_t*)&h0; o.y = *(uint32_t*)&h1;
    o.z = *(uint32_t*)&h2; o.w = *(uint32_t*)&h3;
    *(uint4*)(g_Ah + (size_t)b * 1024 + k) = o;
}

// ---- fp16 tensor-core GEMM: C[M,N] = A[M,K] @ W[N,K]^T, C in fp16 ----------
#define BM 128
#define BN 128
#define BKH 32
#define ROWB 80                        // bytes per smem row (64 + 16 pad)
#define A_ST (BM * ROWB)               // 10240
#define STAGE_B (2 * A_ST)             // 20480
#define STAGES 3
#define HG_SMEM (STAGES * STAGE_B)     // 61440

__global__ void __launch_bounds__(128, 2)
hgemm(int mode)
{
    extern __shared__ char smem[];
    const uint32_t sb = smem_u32(smem);

    const __half* A;
    const __half* W;
    __half* C;
    int lda, N, K;
    if (mode == 0) {
        A = g_Ah;  W = g_G1h; C = g_C1h; lda = G1_K; N = G1_N; K = G1_K;
    } else {
        A = g_RHh; W = g_G2h; C = g_C2h; lda = G2_K; N = G2_N; K = G2_K;
    }

    const int tid  = threadIdx.x;
    const int lane = tid & 31;
    const int wid  = tid >> 5;
    const int wm   = wid & 1;
    const int wn   = wid >> 1;
    const int mBlk = blockIdx.y * BM;
    const int nBlk = blockIdx.x * BN;
    const int NK   = K / BKH;

    // loader: 128 threads; 4 A-rows + 4 B-rows of 16B per stage
    const int lrow = tid >> 2;
    const int seg  = tid & 3;
    const __half* gA[4];
    const __half* gB[4];
    uint32_t sA[4], sB[4];
#pragma unroll
    for (int i = 0; i < 4; ++i) {
        gA[i] = A + (size_t)(mBlk + lrow + 32 * i) * lda + seg * 8;
        gB[i] = W + (size_t)(nBlk + lrow + 32 * i) * K   + seg * 8;
        sA[i] = sb + (lrow + 32 * i) * ROWB + seg * 16;
        sB[i] = sA[i] + A_ST;
    }

    // ldmatrix lane offsets (verified fragment layout)
    const int aRow = lane & 15;
    const int aK   = (lane >> 4) << 3;
    uint32_t aOff[4];
#pragma unroll
    for (int mt = 0; mt < 4; ++mt)
        aOff[mt] = (uint32_t)((wm * 64 + mt * 16 + aRow) * ROWB + aK * 2);
    const int bRow = ((lane >> 4) << 3) + (lane & 7);
    const int bK   = lane & 8;
    uint32_t bOff[4];
#pragma unroll
    for (int p = 0; p < 4; ++p)
        bOff[p] = (uint32_t)(A_ST + (wn * 64 + p * 16 + bRow) * ROWB + bK * 2);

    float c[4][8][4];
#pragma unroll
    for (int i = 0; i < 4; ++i)
#pragma unroll
        for (int j = 0; j < 8; ++j)
#pragma unroll
            for (int r = 0; r < 4; ++r) c[i][j][r] = 0.f;

    auto load = [&](int st, int k) {
        uint32_t off = (uint32_t)(st * STAGE_B);
        int kh = k * BKH;
#pragma unroll
        for (int i = 0; i < 4; ++i) {
            cp16(sA[i] + off, gA[i] + kh);
            cp16(sB[i] + off, gB[i] + kh);
        }
    };

    load(0, 0); cp_commit();
    load(1, 1); cp_commit();

    for (int k = 0; k < NK; ++k) {
        if (k < NK - 1) cp_wait1(); else cp_wait0();
        __syncthreads();

        const uint32_t base = (uint32_t)((k % STAGES) * STAGE_B);

        uint32_t a[2][4][4], b[2][4][4];
#pragma unroll
        for (int mt = 0; mt < 4; ++mt)
            ldsm4(a[0][mt], sb + base + aOff[mt]);
#pragma unroll
        for (int p = 0; p < 4; ++p)
            ldsm4(b[0][p], sb + base + bOff[p]);
#pragma unroll
        for (int mt = 0; mt < 4; ++mt)
            ldsm4(a[1][mt], sb + base + aOff[mt] + 32);
#pragma unroll
        for (int p = 0; p < 4; ++p)
            ldsm4(b[1][p], sb + base + bOff[p] + 32);

        if (k + 2 < NK) {
            load((k + 2) % STAGES, k + 2);
            cp_commit();
        }

#pragma unroll
        for (int kk = 0; kk < 2; ++kk)
#pragma unroll
            for (int mt = 0; mt < 4; ++mt)
#pragma unroll
                for (int nt = 0; nt < 8; ++nt)
                    mma_f16(c[mt][nt], a[kk][mt], &b[kk][nt >> 1][(nt & 1) * 2]);
    }

    // epilogue: fp32 acc -> fp16 C
    const int grp = lane >> 2;
    const int qid = lane & 3;
#pragma unroll
    for (int mt = 0; mt < 4; ++mt) {
#pragma unroll
        for (int nt = 0; nt < 8; ++nt) {
            int row = mBlk + wm * 64 + mt * 16 + grp;
            int col = nBlk + wn * 64 + nt * 8 + qid * 2;
            *(__half2*)&C[(size_t)row * N + col] =
                __floats2half2_rn(c[mt][nt][0], c[mt][nt][1]);
            *(__half2*)&C[(size_t)(row + 8) * N + col] =
                __floats2half2_rn(c[mt][nt][2], c[mt][nt][3]);
        }
    }
}

// ---- elementwise: 4 j per thread ----------------------------------------------
__global__ void e1_kernel(const float* __restrict__ h_re,
                          const float* __restrict__ h_im)
{
    int idx = blockIdx.x * blockDim.x + threadIdx.x;   // < B*64
    int b = idx >> 6;
    int j = (idx & 63) << 2;
    size_t row = (size_t)b * G1_N;

    uint2 cr_u = *(const uint2*)&g_C1h[row + j];
    uint2 ci_u = *(const uint2*)&g_C1h[row + 256 + j];
    const __half* cr = (const __half*)&cr_u;
    const __half* ci = (const __half*)&ci_u;
    float4 br4 = *(const float4*)&g_bias[j];
    float4 bi4 = *(const float4*)&g_bias[256 + j];
    float4 hr4 = *(const float4*)&h_re[(size_t)b * 256 + j];
    float4 hi4 = *(const float4*)&h_im[(size_t)b * 256 + j];
    const float* brp = &br4.x; const float* bip = &bi4.x;
    const float* hrp = &hr4.x; const float* hip = &hi4.x;

    __half rout[4], iout[4];
#pragma unroll
    for (int q = 0; q < 4; ++q) {
        float rr = sigmoidf_(__half2float(cr[q]) + brp[q]);
        float ri = sigmoidf_(__half2float(ci[q]) + bip[q]);
        rout[q] = __float2half(rr * hrp[q] - ri * hip[q]);
        iout[q] = __float2half(rr * hip[q] + ri * hrp[q]);
    }
    size_t r2 = (size_t)b * 512;
    *(uint2*)&g_RHh[r2 + j]       = *(uint2*)rout;
    *(uint2*)&g_RHh[r2 + 256 + j] = *(uint2*)iout;
}

__global__ void e2_kernel(const float* __restrict__ h_re,
                          const float* __restrict__ h_im,
                          float* __restrict__ out)
{
    int idx = blockIdx.x * blockDim.x + threadIdx.x;   // < B*64
    int b = idx >> 6;
    int j = (idx & 63) << 2;
    size_t r1 = (size_t)b * G1_N;
    size_t r2 = (size_t)b * 512;

    uint2 zr_u = *(const uint2*)&g_C1h[r1 + 512 + j];
    uint2 zi_u = *(const uint2*)&g_C1h[r1 + 768 + j];
    uint2 pr_u = *(const uint2*)&g_C1h[r1 + 1024 + j];
    uint2 pi_u = *(const uint2*)&g_C1h[r1 + 1280 + j];
    uint2 c2r_u = *(const uint2*)&g_C2h[r2 + j];
    uint2 c2i_u = *(const uint2*)&g_C2h[r2 + 256 + j];
    const __half* zrh = (const __half*)&zr_u;
    const __half* zih = (const __half*)&zi_u;
    const __half* prh = (const __half*)&pr_u;
    const __half* pih = (const __half*)&pi_u;
    const __half* c2r = (const __half*)&c2r_u;
    const __half* c2i = (const __half*)&c2i_u;

    float4 bzr4 = *(const float4*)&g_bias[512 + j];
    float4 bzi4 = *(const float4*)&g_bias[768 + j];
    float4 bpr4 = *(const float4*)&g_bias[1024 + j];
    float4 bpi4 = *(const float4*)&g_bias[1280 + j];
    float4 hr4  = *(const float4*)&h_re[(size_t)b * 256 + j];
    float4 hi4  = *(const float4*)&h_im[(size_t)b * 256 + j];
    const float* bzr = &bzr4.x; const float* bzi = &bzi4.x;
    const float* bpr = &bpr4.x; const float* bpi = &bpi4.x;
    const float* hrp = &hr4.x;  const float* hip = &hi4.x;

    float ore[4], oim[4];
#pragma unroll
    for (int q = 0; q < 4; ++q) {
        float zr = sigmoidf_(__half2float(zrh[q]) + bzr[q]);
        float zi = sigmoidf_(__half2float(zih[q]) + bzi[q]);
        float er = __half2float(c2r[q]) + __half2float(prh[q]) + bpr[q];
        float ei = __half2float(c2i[q]) + __half2float(pih[q]) + bpi[q];
        float hhr = tanhf(er);
        float hhi = tanhf(ei);
        float hr = hrp[q], hi = hip[q];
        ore[q] = (1.0f - zr) * hr + zi * hi + zr * hhr - zi * hhi;
        oim[q] = (1.0f - zr) * hi - zi * hr + zr * hhi + zi * hhr;
    }
    *(float4*)&out[(size_t)b * 256 + j] = *(float4*)ore;
    *(float4*)&out[(size_t)B_ROWS * HDIM + (size_t)b * 256 + j] = *(float4*)oim;
}

// ---- launch -------------------------------------------------------------------
extern "C" void kernel_launch(void* const* d_in, const int* in_sizes, int n_in,
                              void* d_out, int out_size)
{
    const float* x_re    = (const float*)d_in[0];
    const float* x_im    = (const float*)d_in[1];
    const float* h_re    = (const float*)d_in[2];
    const float* h_im    = (const float*)d_in[3];
    const float* wr_w_re = (const float*)d_in[4];
    const float* wr_w_im = (const float*)d_in[5];
    const float* wr_b_re = (const float*)d_in[6];
    const float* wr_b_im = (const float*)d_in[7];
    const float* wz_w_re = (const float*)d_in[8];
    const float* wz_w_im = (const float*)d_in[9];
    const float* wz_b_re = (const float*)d_in[10];
    const float* wz_b_im = (const float*)d_in[11];
    const float* wh_w_re = (const float*)d_in[12];
    const float* wh_w_im = (const float*)d_in[13];
    const float* wh_b_re = (const float*)d_in[14];
    const float* wh_b_im = (const float*)d_in[15];
    const float* ur_w_re = (const float*)d_in[16];
    const float* ur_w_im = (const float*)d_in[17];
    const float* uz_w_re = (const float*)d_in[18];
    const float* uz_w_im = (const float*)d_in[19];
    const float* uh_w_re = (const float*)d_in[20];
    const float* uh_w_im = (const float*)d_in[21];

    static int smem_set = 0;
    if (!smem_set) {
        cudaFuncSetAttribute(hgemm, cudaFuncAttributeMaxDynamicSharedMemorySize,
                             HG_SMEM);
        smem_set = 1;
    }

    prep_g1<<<(G1_N * 256) / 256, 256>>>(wr_w_re, wr_w_im, wz_w_re, wz_w_im,
                                         wh_w_re, wh_w_im, ur_w_re, ur_w_im,
                                         uz_w_re, uz_w_im, uh_w_re, uh_w_im);
    prep_g2<<<(G2_N * 128) / 256, 256>>>(wh_w_re, wh_w_im);
    prep_bias<<<G1_N / 256, 256>>>(wr_b_re, wr_b_im, wz_b_re, wz_b_im,
                                   wh_b_re, wh_b_im);
    convA<<<(B_ROWS * 128) / 256, 256>>>(x_re, x_im, h_re, h_im);

    dim3 blk(128);
    dim3 grid1(G1_N / BN, B_ROWS / BM);   // 12 x 128
    hgemm<<<grid1, blk, HG_SMEM>>>(0);

    e1_kernel<<<(B_ROWS * 64) / 256, 256>>>(h_re, h_im);

    dim3 grid2(G2_N / BN, B_ROWS / BM);   // 4 x 128
    hgemm<<<grid2, blk, HG_SMEM>>>(1);

    e2_kernel<<<(B_ROWS * 64) / 256, 256>>>(h_re, h_im, (float*)d_out);
}